// round 9
// baseline (speedup 1.0000x reference)
#include <cuda_runtime.h>
#include <cuda_bf16.h>
#include <cstdint>
#include <cstddef>

// CombineGraph: h = emb[inputs]; e_k = leakyrelu(einsum(bid,bjd,d->bij; h,h,a_k));
// alpha = softmax(select_by_adj(e_k, -9e15)); out = alpha @ h.
// B=512, L=100, D=128. One CTA/batch, 2 CTA/SM.
// GEMM1: bf16 m16n8k16; B pre-scaled by all 4 a_k in a half-width ham table
// (2 passes over n); dual-type B fragments via ldmatrix.x4 -> no muls in loop.
// Logits staged in regs (R4/R7-proven), written to f32 al after ham dies.
// GEMM2: tf32 mma.sync; h f32 re-gathered post-softmax into dead smem.

#define B_    512
#define L_    100
#define D_    128
#define NEG_INF_ -9e15f

// ---- smem byte offsets / lifetimes ----
// GEMM1 era : hb[0..27200) atp[27200..28224) ham[28224..86464)
// softmax   : al[53248..98176)            (ham dead)
// GEMM2 era : h[0..53248) al[53248..98176) (hb/atp/ham dead)
#define OFF_HB   0
#define OFF_ATP  27200
#define OFF_HAM  28224
#define OFF_H    0
#define OFF_AL   53248
#define SMEM_TOTAL 98176

#define HBS  68           // hb row stride (words); 272B/row -> 16B bank shift
#define HAMS 260          // ham row stride (words); 1040B/row -> 16B bank shift
#define AS   108          // alpha row stride (floats)

// h f32 swizzle (GEMM2 B): conflict-free for STS.128 write and fragment read
#define HW(r, c) ((r) * 128 + ((c) ^ (((r) & 3) << 3)))

__device__ __forceinline__ uint32_t smem_u32(const void* p) {
    uint32_t a;
    asm("{ .reg .u64 t; cvta.to.shared.u64 t, %1; cvt.u32.u64 %0, t; }" : "=r"(a) : "l"(p));
    return a;
}
__device__ __forceinline__ float rna_tf32(float x) {
    unsigned u; asm("cvt.rna.tf32.f32 %0, %1;" : "=r"(u) : "f"(x));
    return __uint_as_float(u);
}
__device__ __forceinline__ unsigned pack_bf16x2(float lo, float hi) {
    unsigned r; asm("cvt.rn.satfinite.bf16x2.f32 %0, %1, %2;" : "=r"(r) : "f"(hi), "f"(lo));
    return r;
}
__device__ __forceinline__ unsigned mulbf2(unsigned a, unsigned b) {
    unsigned r; asm("mul.bf16x2 %0, %1, %2;" : "=r"(r) : "r"(a), "r"(b));
    return r;
}
__device__ __forceinline__ void ldsm_x4(unsigned& r0, unsigned& r1, unsigned& r2, unsigned& r3,
                                        uint32_t addr) {
    asm volatile("ldmatrix.sync.aligned.m8n8.x4.shared.b16 {%0,%1,%2,%3}, [%4];"
                 : "=r"(r0), "=r"(r1), "=r"(r2), "=r"(r3) : "r"(addr));
}
__device__ __forceinline__ void mma_bf16(float* c, unsigned a0, unsigned a1,
                                         unsigned a2, unsigned a3,
                                         unsigned b0, unsigned b1) {
    asm volatile(
        "mma.sync.aligned.m16n8k16.row.col.f32.bf16.bf16.f32 "
        "{%0,%1,%2,%3},{%4,%5,%6,%7},{%8,%9},{%0,%1,%2,%3};\n"
        : "+f"(c[0]), "+f"(c[1]), "+f"(c[2]), "+f"(c[3])
        : "r"(a0), "r"(a1), "r"(a2), "r"(a3), "r"(b0), "r"(b1));
}
__device__ __forceinline__ void mma_tf32(float* c, const unsigned* a, unsigned b0, unsigned b1) {
    asm volatile(
        "mma.sync.aligned.m16n8k8.row.col.f32.tf32.tf32.f32 "
        "{%0,%1,%2,%3},{%4,%5,%6,%7},{%8,%9},{%0,%1,%2,%3};\n"
        : "+f"(c[0]), "+f"(c[1]), "+f"(c[2]), "+f"(c[3])
        : "r"(a[0]), "r"(a[1]), "r"(a[2]), "r"(a[3]), "r"(b0), "r"(b1));
}

// Build ham for j-rows [j0g, j0g+nrows): ham[jl][t*64+wd] = bf16(h[j0g+jl]) * a_t
__device__ __forceinline__ void build_ham(char* smem, int j0g, int nrows, int tid) {
    const uint4* hb4  = (const uint4*)(smem + OFF_HB);
    const uint4* atp4 = (const uint4*)(smem + OFF_ATP);
    uint4*       ham4 = (uint4*)(smem + OFF_HAM);
    for (int e = tid; e < nrows * 16; e += 512) {
        int jl = e >> 4, wdq = e & 15;
        int jg = j0g + jl;
        uint4 h4 = make_uint4(0, 0, 0, 0);
        if (jg < L_) h4 = hb4[jl ? (jg * 17 + wdq) : (jg * 17 + wdq)];
        #pragma unroll
        for (int t = 0; t < 4; ++t) {
            uint4 a4 = atp4[t * 16 + wdq];
            uint4 o;
            o.x = mulbf2(h4.x, a4.x); o.y = mulbf2(h4.y, a4.y);
            o.z = mulbf2(h4.z, a4.z); o.w = mulbf2(h4.w, a4.w);
            ham4[jl * 65 + t * 16 + wdq] = o;
        }
    }
}

// One GEMM1 job: m16 tile mt, n8 tile nt (cols colbase + nt*8 .. +7).
// Result: stg[2] = bf16x2-packed selected logits for (hf=0,1) x (e=0,1).
__device__ __forceinline__ void gemm1_job(const int* adjb,
                                          int mt, int nt, int colbase,
                                          uint32_t hb_u, uint32_t ham_u,
                                          int lane, int g, int t4,
                                          unsigned* stg) {
    // adj prefetch (gmem, L2-hot)
    const int grow0 = mt * 16 + g;
    const int gc0   = colbase + nt * 8 + 2 * t4;
    int2 adjv[2];
    adjv[0] = make_int2(0, 0); adjv[1] = make_int2(0, 0);
    if (gc0 < L_) {
        if (grow0 < L_)     adjv[0] = *(const int2*)(adjb + grow0 * L_ + gc0);
        if (grow0 + 8 < L_) adjv[1] = *(const int2*)(adjb + (grow0 + 8) * L_ + gc0);
    }
    // fragment addresses
    int ra = mt * 16 + (lane & 15);
    if (ra > 99) ra = 99;                    // rows >= 100 clamped (results discarded)
    uint32_t a_addr = hb_u + (uint32_t)(ra * (HBS * 4)) + (uint32_t)((lane >> 4) << 4);
    uint32_t b_addr = ham_u + (uint32_t)((nt * 8 + (lane & 7)) * (HAMS * 4))
                            + (uint32_t)(((lane >> 3) & 1) << 4)
                            + (uint32_t)((lane >> 4) << 8);
    float c[4][4];
    #pragma unroll
    for (int t = 0; t < 4; ++t)
        #pragma unroll
        for (int p = 0; p < 4; ++p) c[t][p] = 0.f;

    #pragma unroll
    for (int ks = 0; ks < 8; ++ks) {
        unsigned A0, A1, A2, A3, B0, B1, B2, B3, B4, B5, B6, B7;
        ldsm_x4(A0, A1, A2, A3, a_addr + ks * 32u);
        ldsm_x4(B0, B1, B2, B3, b_addr + ks * 32u);           // types 0,1
        ldsm_x4(B4, B5, B6, B7, b_addr + 512u + ks * 32u);    // types 2,3
        mma_bf16(c[0], A0, A1, A2, A3, B0, B1);
        mma_bf16(c[1], A0, A1, A2, A3, B2, B3);
        mma_bf16(c[2], A0, A1, A2, A3, B4, B5);
        mma_bf16(c[3], A0, A1, A2, A3, B6, B7);
    }
    // select by adj + leaky-relu -> staged bf16x2 (default NEG_INF)
    #pragma unroll
    for (int hf = 0; hf < 2; ++hf) {
        int2 av = adjv[hf];
        float v[2];
        #pragma unroll
        for (int e = 0; e < 2; ++e) {
            int t = e ? av.y : av.x;
            float x = (t == 1) ? c[0][2 * hf + e] :
                      (t == 2) ? c[1][2 * hf + e] :
                      (t == 3) ? c[2][2 * hf + e] :
                      (t == 4) ? c[3][2 * hf + e] : 0.f;
            x = (x > 0.f) ? x : 0.2f * x;
            v[e] = t ? x : NEG_INF_;
        }
        stg[hf] = pack_bf16x2(v[0], v[1]);
    }
}

__device__ __forceinline__ void stg_writeback(float* al_sm, int mt, int nt, int colbase,
                                              int g, int t4, const unsigned* stg) {
    int col0 = colbase + nt * 8 + 2 * t4;    // <= 102, always < 104
    #pragma unroll
    for (int hf = 0; hf < 2; ++hf) {
        int row = mt * 16 + g + 8 * hf;
        if (row < 104) {
            unsigned pk = stg[hf];
            float2 vv = make_float2(__uint_as_float(pk << 16),
                                    __uint_as_float(pk & 0xffff0000u));
            *(float2*)(al_sm + row * AS + col0) = vv;
        }
    }
}

__global__ __launch_bounds__(512, 2)
void combine_graph_kernel(const int* __restrict__ inputs,
                          const int* __restrict__ adj,
                          const float* __restrict__ emb,
                          const float* __restrict__ a0p,
                          const float* __restrict__ a1p,
                          const float* __restrict__ a2p,
                          const float* __restrict__ a3p,
                          float* __restrict__ out)
{
    extern __shared__ char smem[];
    unsigned* hb_sm  = (unsigned*)(smem + OFF_HB);
    unsigned* atp_sm = (unsigned*)(smem + OFF_ATP);
    float*    al_sm  = (float*)(smem + OFF_AL);
    float*    h_sm   = (float*)(smem + OFF_H);
    const uint32_t hb_u  = smem_u32(smem + OFF_HB);
    const uint32_t ham_u = smem_u32(smem + OFF_HAM);

    const int b    = blockIdx.x;
    const int tid  = threadIdx.x;
    const int w    = tid >> 5;
    const int lane = tid & 31;
    const int g    = lane >> 2;
    const int t4   = lane & 3;

    const int* inp  = inputs + b * L_;
    const int* adjb = adj + (size_t)b * (L_ * L_);

    // ---------------- phase 0: hb gather + atpT ----------------
    if (tid < 256) {   // atpT[t][wd]
        int t = tid >> 6, wd = tid & 63;
        const float* ap = (t == 0) ? a0p : (t == 1) ? a1p : (t == 2) ? a2p : a3p;
        atp_sm[t * 64 + wd] = pack_bf16x2(ap[2 * wd], ap[2 * wd + 1]);
    }
    for (int e = tid; e < 100 * 32; e += 512) {
        int r = e >> 5, q = e & 31;
        int id = inp[r];
        float4 v = ((const float4*)(emb + (size_t)id * D_))[q];
        uint2 p2 = make_uint2(pack_bf16x2(v.x, v.y), pack_bf16x2(v.z, v.w));
        *(uint2*)(hb_sm + r * HBS + 2 * q) = p2;
    }
    __syncthreads();

    // ---------------- GEMM1 pass 1: cols 0..47 (42 jobs: 7mt x 6nt) ----------------
    unsigned stg1[3][2], stg2[4][2];
    build_ham(smem, 0, 48, tid);
    __syncthreads();
    #pragma unroll
    for (int k = 0; k < 3; ++k) {
        int job = w + 16 * k;
        if (job < 42)
            gemm1_job(adjb, job / 6, job % 6, 0, hb_u, ham_u, lane, g, t4, stg1[k]);
    }
    __syncthreads();

    // ---------------- GEMM1 pass 2: cols 48..103 (49 jobs: 7mt x 7nt) ----------------
    build_ham(smem, 48, 56, tid);
    __syncthreads();
    #pragma unroll
    for (int k = 0; k < 3; ++k) {
        int job = w + 16 * k;   // 0..47
        gemm1_job(adjb, job / 7, job % 7, 48, hb_u, ham_u, lane, g, t4, stg2[k]);
    }
    if (w == 15)
        gemm1_job(adjb, 6, 6, 48, hb_u, ham_u, lane, g, t4, stg2[3]);
    __syncthreads();   // ham dead; al overlay valid

    // ---------------- writeback staged logits -> al (f32) ----------------
    #pragma unroll
    for (int k = 0; k < 3; ++k) {
        int job = w + 16 * k;
        if (job < 42) stg_writeback(al_sm, job / 6, job % 6, 0, g, t4, stg1[k]);
    }
    #pragma unroll
    for (int k = 0; k < 3; ++k) {
        int job = w + 16 * k;
        stg_writeback(al_sm, job / 7, job % 7, 48, g, t4, stg2[k]);
    }
    if (w == 15) stg_writeback(al_sm, 6, 6, 48, g, t4, stg2[3]);
    __syncthreads();

    // ---------------- softmax over j (R7-proven) ----------------
    for (int i = w; i < L_; i += 16) {
        float x[4];
        #pragma unroll
        for (int q = 0; q < 4; ++q) {
            int j = lane + 32 * q;
            x[q] = (j < 104) ? al_sm[i * AS + j] : NEG_INF_;
        }
        float mx = fmaxf(fmaxf(x[0], x[1]), fmaxf(x[2], x[3]));
        #pragma unroll
        for (int o = 16; o > 0; o >>= 1) mx = fmaxf(mx, __shfl_xor_sync(0xffffffffu, mx, o));
        float ev[4], s = 0.f;
        #pragma unroll
        for (int q = 0; q < 4; ++q) {
            int j = lane + 32 * q;
            ev[q] = (j < L_) ? __expf(x[q] - mx) : 0.f;
            s += ev[q];
        }
        #pragma unroll
        for (int o = 16; o > 0; o >>= 1) s += __shfl_xor_sync(0xffffffffu, s, o);
        float inv = 1.f / s;
        #pragma unroll
        for (int q = 0; q < 4; ++q) {
            int j = lane + 32 * q;
            if (j < L_)       al_sm[i * AS + j] = rna_tf32(ev[q] * inv);
            else if (j < 104) al_sm[i * AS + j] = 0.f;
        }
    }
    // zero alpha rows 100..103 (GEMM2 K padding)
    for (int e = tid; e < 4 * AS; e += 512) al_sm[L_ * AS + e] = 0.f;
    __syncthreads();

    // ---------------- re-gather h f32 (tf32, swizzled) for GEMM2 ----------------
    for (int e = tid; e < 104 * 32; e += 512) {
        int r = e >> 5, q = e & 31;
        float4 v = make_float4(0.f, 0.f, 0.f, 0.f);
        if (r < L_) {
            int id = inp[r];
            v = ((const float4*)(emb + (size_t)id * D_))[q];
            v.x = rna_tf32(v.x); v.y = rna_tf32(v.y);
            v.z = rna_tf32(v.z); v.w = rna_tf32(v.w);
        }
        *(float4*)(h_sm + HW(r, 4 * q)) = v;
    }
    __syncthreads();

    // ---------------- GEMM2: out = alpha @ h (tf32) ----------------
    {
        const int i32 = w & 3;
        const int ntq = w >> 2;
        const int r0b = i32 * 32;
        const int nh2 = (i32 == 3) ? 1 : 2;
        float c2[4][2][4];
        #pragma unroll
        for (int n = 0; n < 4; ++n)
            #pragma unroll
            for (int h = 0; h < 2; ++h)
                #pragma unroll
                for (int r = 0; r < 4; ++r) c2[n][h][r] = 0.f;

        #pragma unroll 4
        for (int kt = 0; kt < 13; ++kt) {
            int col = kt * 8 + t4;
            unsigned A2[2][4];
            #pragma unroll
            for (int h = 0; h < 2; ++h) {
                if (h < nh2) {
                    int r = r0b + h * 16 + g;
                    A2[h][0] = __float_as_uint(al_sm[r * AS + col]);
                    A2[h][1] = (i32 == 3) ? 0u : __float_as_uint(al_sm[(r + 8) * AS + col]);
                    A2[h][2] = __float_as_uint(al_sm[r * AS + col + 4]);
                    A2[h][3] = (i32 == 3) ? 0u : __float_as_uint(al_sm[(r + 8) * AS + col + 4]);
                }
            }
            #pragma unroll
            for (int n = 0; n < 4; ++n) {
                int d = (ntq * 4 + n) * 8 + g;
                unsigned B0 = __float_as_uint(h_sm[HW(col, d)]);
                unsigned B1 = __float_as_uint(h_sm[HW(col + 4, d)]);
                mma_tf32(c2[n][0], A2[0], B0, B1);
                if (nh2 == 2) mma_tf32(c2[n][1], A2[1], B0, B1);
            }
        }
        float* outb = out + (size_t)b * (L_ * D_);
        #pragma unroll
        for (int n = 0; n < 4; ++n) {
            #pragma unroll
            for (int h = 0; h < 2; ++h) {
                if (h < nh2) {
                    #pragma unroll
                    for (int p = 0; p < 2; ++p) {
                        int row = r0b + h * 16 + g + p * 8;
                        if (row < L_) {
                            int colo = (ntq * 4 + n) * 8 + t4 * 2;
                            float2 v2 = make_float2(c2[n][h][p * 2], c2[n][h][p * 2 + 1]);
                            *(float2*)(outb + row * D_ + colo) = v2;
                        }
                    }
                }
            }
        }
    }
}

extern "C" void kernel_launch(void* const* d_in, const int* in_sizes, int n_in,
                              void* d_out, int out_size) {
    // metadata order: inputs, adj, mask_item, item, emb_table, a0, a1, a2, a3
    const int*   inputs = (const int*)d_in[0];
    const int*   adj    = (const int*)d_in[1];
    const float* emb    = (const float*)d_in[4];
    const float* a0     = (const float*)d_in[5];
    const float* a1     = (const float*)d_in[6];
    const float* a2     = (const float*)d_in[7];
    const float* a3     = (const float*)d_in[8];
    float* out = (float*)d_out;

    cudaFuncSetAttribute(combine_graph_kernel,
                         cudaFuncAttributeMaxDynamicSharedMemorySize, SMEM_TOTAL);

    combine_graph_kernel<<<B_, 512, SMEM_TOTAL>>>(inputs, adj, emb, a0, a1, a2, a3, out);
}

// round 10
// speedup vs baseline: 1.1554x; 1.1554x over previous
#include <cuda_runtime.h>
#include <cuda_bf16.h>
#include <cstdint>
#include <cstddef>

// CombineGraph: h = emb[inputs]; e_k = leakyrelu(einsum(bid,bjd,d->bij; h,h,a_k));
// alpha = softmax(select_by_adj(e_k, -9e15)); out = alpha @ h.
// B=512, L=100, D=128. One CTA/batch, 2 CTA/SM (R7 layout, all operands resident).
// GEMM1 exploits e_k symmetry: only 28 upper-triangle m16xn16 tiles computed
// (vs 49); epilogue writes direct + mirrored entries with their own adj select.
// bf16 m16n8k16 via ldmatrix (A x4, B x4 dual-tile), a_k scaling in-loop.
// GEMM2: tf32 mma.sync, swizzled resident h f32.

#define B_    512
#define L_    100
#define D_    128
#define HB    68         // hb row stride (u32 words): 272B/row -> ldmatrix conflict-free
#define AS    108        // alpha row stride (floats)
#define ADJS  112        // adj row stride (bytes)
#define NEG_INF_ -9e15f

// ---- smem byte offsets ----
#define OFF_H    0            // h f32 swizzled: 104*128*4 = 53248 (resident throughout)
#define OFF_HB   53248        // hb bf16: 104*68*4 = 28288
#define OFF_ATP  81536        // a packed uint4[64] = 1024
#define OFF_ADJ  82560        // adj int8: 100*112 = 11200 (end 93760)
#define OFF_AL   53248        // alpha overlays hb/atp/adj: 104*108*4 = 44928 (end 98176)
#define SMEM_TOTAL 98176

// h f32 swizzle: conflict-free for STS.128 write and GEMM2 B-fragment read
#define HW(r, c) ((r) * 128 + ((c) ^ (((r) & 3) << 3)))

__device__ __forceinline__ uint32_t smem_u32(const void* p) {
    uint32_t a;
    asm("{ .reg .u64 t; cvta.to.shared.u64 t, %1; cvt.u32.u64 %0, t; }" : "=r"(a) : "l"(p));
    return a;
}
__device__ __forceinline__ float rna_tf32(float x) {
    unsigned u; asm("cvt.rna.tf32.f32 %0, %1;" : "=r"(u) : "f"(x));
    return __uint_as_float(u);
}
__device__ __forceinline__ unsigned pack_bf16x2(float lo, float hi) {
    unsigned r; asm("cvt.rn.satfinite.bf16x2.f32 %0, %1, %2;" : "=r"(r) : "f"(hi), "f"(lo));
    return r;
}
__device__ __forceinline__ unsigned mulbf2(unsigned a, unsigned b) {
    unsigned r; asm("mul.bf16x2 %0, %1, %2;" : "=r"(r) : "r"(a), "r"(b));
    return r;
}
__device__ __forceinline__ void ldsm_x4(unsigned& r0, unsigned& r1, unsigned& r2, unsigned& r3,
                                        uint32_t addr) {
    asm volatile("ldmatrix.sync.aligned.m8n8.x4.shared.b16 {%0,%1,%2,%3}, [%4];"
                 : "=r"(r0), "=r"(r1), "=r"(r2), "=r"(r3) : "r"(addr));
}
__device__ __forceinline__ void mma_bf16(float* c, unsigned a0, unsigned a1,
                                         unsigned a2, unsigned a3,
                                         unsigned b0, unsigned b1) {
    asm volatile(
        "mma.sync.aligned.m16n8k16.row.col.f32.bf16.bf16.f32 "
        "{%0,%1,%2,%3},{%4,%5,%6,%7},{%8,%9},{%0,%1,%2,%3};\n"
        : "+f"(c[0]), "+f"(c[1]), "+f"(c[2]), "+f"(c[3])
        : "r"(a0), "r"(a1), "r"(a2), "r"(a3), "r"(b0), "r"(b1));
}
__device__ __forceinline__ void mma_tf32(float* c, const unsigned* a, unsigned b0, unsigned b1) {
    asm volatile(
        "mma.sync.aligned.m16n8k8.row.col.f32.tf32.tf32.f32 "
        "{%0,%1,%2,%3},{%4,%5,%6,%7},{%8,%9},{%0,%1,%2,%3};\n"
        : "+f"(c[0]), "+f"(c[1]), "+f"(c[2]), "+f"(c[3])
        : "r"(a[0]), "r"(a[1]), "r"(a[2]), "r"(a[3]), "r"(b0), "r"(b1));
}

// triangle decode: jobs 0..27 -> (mt, np) with np >= mt; per-mt counts 7..1
__device__ __forceinline__ void decode_job(int job, int& mt, int& np) {
    mt = (job >= 27) ? 6 : (job >= 25) ? 5 : (job >= 22) ? 4 :
         (job >= 18) ? 3 : (job >= 13) ? 2 : (job >= 7) ? 1 : 0;
    int base = (mt == 6) ? 27 : (mt == 5) ? 25 : (mt == 4) ? 22 :
               (mt == 3) ? 18 : (mt == 2) ? 13 : (mt == 1) ? 7 : 0;
    np = mt + (job - base);
}

// One GEMM1 tile job (mt, np>=mt). Stages direct + mirrored selected logits.
__device__ __forceinline__ void gemm1_job(char* smem, int mt, int np,
                                          uint32_t hb_u, int lane, int g, int t4,
                                          unsigned stgD[2][2], unsigned stgM[2][2]) {
    const char*  adj_sm = smem + OFF_ADJ;
    const uint4* atp4   = (const uint4*)(smem + OFF_ATP);
    const int r0 = mt * 16, jc0 = np * 16;

    int ra = r0 + (lane & 15);  if (ra > 103) ra = 103;
    int rb = jc0 + (lane & 15); if (rb > 103) rb = 103;   // np==6 clamp: cols discarded
    uint32_t a_addr = hb_u + (uint32_t)(ra * HB + ((lane >> 4) << 2)) * 4u;
    uint32_t b_addr = hb_u + (uint32_t)(rb * HB + ((lane >> 4) << 2)) * 4u;
    const uint4* pt = atp4 + t4;

    float c[2][4][4];
    #pragma unroll
    for (int nn = 0; nn < 2; ++nn)
        #pragma unroll
        for (int k = 0; k < 4; ++k)
            #pragma unroll
            for (int p = 0; p < 4; ++p) c[nn][k][p] = 0.f;

    #pragma unroll 2
    for (int ks = 0; ks < 8; ++ks) {
        unsigned A0, A1, A2, A3, B0, B1, B2, B3;
        ldsm_x4(A0, A1, A2, A3, a_addr + ks * 32u);
        ldsm_x4(B0, B1, B2, B3, b_addr + ks * 32u);   // nn0:(B0,B2) nn1:(B1,B3)
        uint4 ap0 = pt[ks * 8];
        uint4 ap1 = pt[ks * 8 + 4];
        mma_bf16(c[0][0], A0, A1, A2, A3, mulbf2(B0, ap0.x), mulbf2(B2, ap1.x));
        mma_bf16(c[0][1], A0, A1, A2, A3, mulbf2(B0, ap0.y), mulbf2(B2, ap1.y));
        mma_bf16(c[0][2], A0, A1, A2, A3, mulbf2(B0, ap0.z), mulbf2(B2, ap1.z));
        mma_bf16(c[0][3], A0, A1, A2, A3, mulbf2(B0, ap0.w), mulbf2(B2, ap1.w));
        mma_bf16(c[1][0], A0, A1, A2, A3, mulbf2(B1, ap0.x), mulbf2(B3, ap1.x));
        mma_bf16(c[1][1], A0, A1, A2, A3, mulbf2(B1, ap0.y), mulbf2(B3, ap1.y));
        mma_bf16(c[1][2], A0, A1, A2, A3, mulbf2(B1, ap0.z), mulbf2(B3, ap1.z));
        mma_bf16(c[1][3], A0, A1, A2, A3, mulbf2(B1, ap0.w), mulbf2(B3, ap1.w));
    }

    // epilogue: select by adj (direct) and adj^T (mirror), leaky-relu, stage bf16x2
    #pragma unroll
    for (int nn = 0; nn < 2; ++nn) {
        #pragma unroll
        for (int hf = 0; hf < 2; ++hf) {
            int row = r0 + g + 8 * hf;
            float vD[2], vM[2];
            #pragma unroll
            for (int e = 0; e < 2; ++e) {
                int col = jc0 + 8 * nn + 2 * t4 + e;
                int p = 2 * hf + e;
                float xD = NEG_INF_, xM = NEG_INF_;
                if (row < L_ && col < L_) {
                    int t = adj_sm[row * ADJS + col];
                    float x = (t == 1) ? c[nn][0][p] : (t == 2) ? c[nn][1][p] :
                              (t == 3) ? c[nn][2][p] : (t == 4) ? c[nn][3][p] : 0.f;
                    x = (x > 0.f) ? x : 0.2f * x;
                    xD = t ? x : NEG_INF_;
                    int tm = adj_sm[col * ADJS + row];
                    float y = (tm == 1) ? c[nn][0][p] : (tm == 2) ? c[nn][1][p] :
                              (tm == 3) ? c[nn][2][p] : (tm == 4) ? c[nn][3][p] : 0.f;
                    y = (y > 0.f) ? y : 0.2f * y;
                    xM = tm ? y : NEG_INF_;
                }
                vD[e] = xD; vM[e] = xM;
            }
            stgD[nn][hf] = pack_bf16x2(vD[0], vD[1]);
            stgM[nn][hf] = pack_bf16x2(vM[0], vM[1]);
        }
    }
}

__device__ __forceinline__ void wb_job(float* al_sm, int mt, int np, int g, int t4,
                                       const unsigned stgD[2][2], const unsigned stgM[2][2]) {
    const int r0 = mt * 16, jc0 = np * 16;
    #pragma unroll
    for (int nn = 0; nn < 2; ++nn) {
        int col0 = jc0 + 8 * nn + 2 * t4;
        #pragma unroll
        for (int hf = 0; hf < 2; ++hf) {
            int row = r0 + g + 8 * hf;
            if (row < 104 && col0 < 104) {
                unsigned pk = stgD[nn][hf];
                *(float2*)(al_sm + row * AS + col0) =
                    make_float2(__uint_as_float(pk << 16),
                                __uint_as_float(pk & 0xffff0000u));
            }
            if (np > mt && row < L_) {        // mirror into strictly-lower triangle
                unsigned pk = stgM[nn][hf];
                if (col0 < L_)     al_sm[col0 * AS + row]       = __uint_as_float(pk << 16);
                if (col0 + 1 < L_) al_sm[(col0 + 1) * AS + row] = __uint_as_float(pk & 0xffff0000u);
            }
        }
    }
}

__global__ __launch_bounds__(512, 2)
void combine_graph_kernel(const int* __restrict__ inputs,
                          const int* __restrict__ adj,
                          const float* __restrict__ emb,
                          const float* __restrict__ a0p,
                          const float* __restrict__ a1p,
                          const float* __restrict__ a2p,
                          const float* __restrict__ a3p,
                          float* __restrict__ out)
{
    extern __shared__ char smem[];
    float*    h_sm   = (float*)(smem + OFF_H);
    unsigned* hb_sm  = (unsigned*)(smem + OFF_HB);
    unsigned* atp_sm = (unsigned*)(smem + OFF_ATP);
    char*     adj_sm = smem + OFF_ADJ;
    float*    al_sm  = (float*)(smem + OFF_AL);
    const uint32_t hb_u = smem_u32(smem + OFF_HB);

    const int b    = blockIdx.x;
    const int tid  = threadIdx.x;
    const int w    = tid >> 5;
    const int lane = tid & 31;
    const int g    = lane >> 2;
    const int t4   = lane & 3;

    const int* inp  = inputs + b * L_;
    const int* adjb = adj + (size_t)b * (L_ * L_);

    // ---------------- phase 0: loads ----------------
    if (tid < 256) {   // atp[wd] = {pack(a0),pack(a1),pack(a2),pack(a3)} for word wd
        int wd = tid & 63, k = tid >> 6;
        const float* ap = (k == 0) ? a0p : (k == 1) ? a1p : (k == 2) ? a2p : a3p;
        ((unsigned*)((uint4*)atp_sm + wd))[k] = pack_bf16x2(ap[2 * wd], ap[2 * wd + 1]);
    }
    // embedding gather -> h f32 (tf32, swizzled) + hb bf16; rows 100..103 zero
    for (int e = tid; e < 104 * 32; e += 512) {
        int r = e >> 5, q = e & 31;
        float4 v = make_float4(0.f, 0.f, 0.f, 0.f);
        if (r < L_) {
            int id = inp[r];
            v = ((const float4*)(emb + (size_t)id * D_))[q];
            v.x = rna_tf32(v.x); v.y = rna_tf32(v.y);
            v.z = rna_tf32(v.z); v.w = rna_tf32(v.w);
        }
        *(float4*)(h_sm + HW(r, 4 * q)) = v;
        uint2 p2 = make_uint2(pack_bf16x2(v.x, v.y), pack_bf16x2(v.z, v.w));
        *(uint2*)(hb_sm + r * HB + 2 * q) = p2;
    }
    // adj -> int8
    for (int e = tid; e < 2500; e += 512) {
        int i = e / 25, c = e % 25;
        int4 v = ((const int4*)(adjb + i * 100))[c];
        unsigned p = (unsigned)(v.x & 0xff) | ((unsigned)(v.y & 0xff) << 8)
                   | ((unsigned)(v.z & 0xff) << 16) | ((unsigned)(v.w & 0xff) << 24);
        *(unsigned*)(adj_sm + i * ADJS + c * 4) = p;
    }
    __syncthreads();

    // ---------- GEMM1: 28 upper-triangle tiles, 2 rounds over 16 warps ----------
    unsigned stgD[2][2][2], stgM[2][2][2];
    #pragma unroll
    for (int k = 0; k < 2; ++k) {
        int job = w + 16 * k;
        if (job < 28) {
            int mt, np; decode_job(job, mt, np);
            gemm1_job(smem, mt, np, hb_u, lane, g, t4, stgD[k], stgM[k]);
        }
    }
    __syncthreads();   // hb/atp/adj dead; al overlay valid

    #pragma unroll
    for (int k = 0; k < 2; ++k) {
        int job = w + 16 * k;
        if (job < 28) {
            int mt, np; decode_job(job, mt, np);
            wb_job(al_sm, mt, np, g, t4, stgD[k], stgM[k]);
        }
    }
    __syncthreads();

    // ---------------- softmax over j ----------------
    for (int i = w; i < L_; i += 16) {
        float x[4];
        #pragma unroll
        for (int q = 0; q < 4; ++q) {
            int j = lane + 32 * q;
            x[q] = (j < L_) ? al_sm[i * AS + j] : NEG_INF_;   // padding cols not written
        }
        float mx = fmaxf(fmaxf(x[0], x[1]), fmaxf(x[2], x[3]));
        #pragma unroll
        for (int o = 16; o > 0; o >>= 1) mx = fmaxf(mx, __shfl_xor_sync(0xffffffffu, mx, o));
        float ev[4], s = 0.f;
        #pragma unroll
        for (int q = 0; q < 4; ++q) {
            int j = lane + 32 * q;
            ev[q] = (j < L_) ? __expf(x[q] - mx) : 0.f;
            s += ev[q];
        }
        #pragma unroll
        for (int o = 16; o > 0; o >>= 1) s += __shfl_xor_sync(0xffffffffu, s, o);
        float inv = 1.f / s;
        #pragma unroll
        for (int q = 0; q < 4; ++q) {
            int j = lane + 32 * q;
            if (j < L_)       al_sm[i * AS + j] = rna_tf32(ev[q] * inv);
            else if (j < 104) al_sm[i * AS + j] = 0.f;        // GEMM2 padding cols
        }
    }
    // zero alpha rows 100..103 (GEMM2 K padding)
    for (int e = tid; e < 4 * AS; e += 512) al_sm[L_ * AS + e] = 0.f;
    __syncthreads();

    // ---------------- GEMM2: out = alpha @ h (tf32) ----------------
    {
        const int i32 = w & 3;
        const int ntq = w >> 2;
        const int r0b = i32 * 32;
        const int nh2 = (i32 == 3) ? 1 : 2;
        float c2[4][2][4];
        #pragma unroll
        for (int n = 0; n < 4; ++n)
            #pragma unroll
            for (int h = 0; h < 2; ++h)
                #pragma unroll
                for (int r = 0; r < 4; ++r) c2[n][h][r] = 0.f;

        #pragma unroll 4
        for (int kt = 0; kt < 13; ++kt) {
            int col = kt * 8 + t4;
            unsigned A2[2][4];
            #pragma unroll
            for (int h = 0; h < 2; ++h) {
                if (h < nh2) {
                    int r = r0b + h * 16 + g;
                    A2[h][0] = __float_as_uint(al_sm[r * AS + col]);
                    A2[h][1] = (i32 == 3) ? 0u : __float_as_uint(al_sm[(r + 8) * AS + col]);
                    A2[h][2] = __float_as_uint(al_sm[r * AS + col + 4]);
                    A2[h][3] = (i32 == 3) ? 0u : __float_as_uint(al_sm[(r + 8) * AS + col + 4]);
                }
            }
            #pragma unroll
            for (int n = 0; n < 4; ++n) {
                int d = (ntq * 4 + n) * 8 + g;
                unsigned B0 = __float_as_uint(h_sm[HW(col, d)]);
                unsigned B1 = __float_as_uint(h_sm[HW(col + 4, d)]);
                mma_tf32(c2[n][0], A2[0], B0, B1);
                if (nh2 == 2) mma_tf32(c2[n][1], A2[1], B0, B1);
            }
        }
        float* outb = out + (size_t)b * (L_ * D_);
        #pragma unroll
        for (int n = 0; n < 4; ++n) {
            #pragma unroll
            for (int h = 0; h < 2; ++h) {
                if (h < nh2) {
                    #pragma unroll
                    for (int p = 0; p < 2; ++p) {
                        int row = r0b + h * 16 + g + p * 8;
                        if (row < L_) {
                            int colo = (ntq * 4 + n) * 8 + t4 * 2;
                            float2 v2 = make_float2(c2[n][h][p * 2], c2[n][h][p * 2 + 1]);
                            *(float2*)(outb + row * D_ + colo) = v2;
                        }
                    }
                }
            }
        }
    }
}

extern "C" void kernel_launch(void* const* d_in, const int* in_sizes, int n_in,
                              void* d_out, int out_size) {
    // metadata order: inputs, adj, mask_item, item, emb_table, a0, a1, a2, a3
    const int*   inputs = (const int*)d_in[0];
    const int*   adj    = (const int*)d_in[1];
    const float* emb    = (const float*)d_in[4];
    const float* a0     = (const float*)d_in[5];
    const float* a1     = (const float*)d_in[6];
    const float* a2     = (const float*)d_in[7];
    const float* a3     = (const float*)d_in[8];
    float* out = (float*)d_out;

    cudaFuncSetAttribute(combine_graph_kernel,
                         cudaFuncAttributeMaxDynamicSharedMemorySize, SMEM_TOTAL);

    combine_graph_kernel<<<B_, 512, SMEM_TOTAL>>>(inputs, adj, emb, a0, a1, a2, a3, out);
}